// round 8
// baseline (speedup 1.0000x reference)
#include <cuda_runtime.h>

#define N_PH  1024
#define IMG   256
#define NPIX  (IMG * IMG)
#define TW    32          // tile width  (pixels)
#define TH    8           // tile height (pixels)
#define CAP   512         // max survivors per tile (union of both batches, ~200 worst)

// Constants from the reference
#define C_SPREAD_INV  (1.0f / 0.000675f)
#define C_R2S         0.5f
#define C_SLOPE       19152642.5f
#define C_HALF        1.057e-07f
#define C_RHEO        2.39e-05f
#define C_PWF         (0.00017f * 300.0f)
#define C_ISCALE      8e-05f
#define HALF_LOG2E    0.72134752f   // log2(e)/2 ; exp(-d2/2s2) = exp2(-HALF_LOG2E*d2/s2)

// Single-instruction exp2 (MUFU.EX2), independent of compiler fast-math flags.
__device__ __forceinline__ float ex2_approx(float x) {
    float r;
    asm("ex2.approx.f32 %0, %1;" : "=f"(r) : "f"(x));
    return r;
}

__global__ void __launch_bounds__(256)
fused_kernel(const float* __restrict__ stim,
             const float* __restrict__ vx,
             const float* __restrict__ vy,
             const float* __restrict__ Marr,
             const float* __restrict__ px,
             const float* __restrict__ py,
             const int*   __restrict__ idx,
             float*       __restrict__ out)
{
    __shared__ float4 shA[CAP];   // cxs, cys, m0, m1
    __shared__ float2 shB[CAP];   // Bw0*? , Bw1  (x2 output scale folded in)
    __shared__ int    cnt;

    const int tid  = threadIdx.x;
    const int tile = blockIdx.x;           // 0..255 : 8 x-tiles * 32 y-tiles
    const int tx0  = (tile & 7)  * TW;
    const int ty0  = (tile >> 3) * TH;

    if (tid == 0) cnt = 0;

    // fov = px.max() = last element of ascending linspace
    const float fov = px[NPIX - 1];
    const float d2p = (float)IMG / (2.0f * fov);   // deg2pix

    // Scaled pixel coordinate of column w: px[w]*d2p == w*(256/255) - 128 (±ulp).
    // Approximation error (~1e-3 px) is absorbed by the 6-sigma footprint.
    const float PSTEP = 256.0f / 255.0f;
    const float bxlo = tx0 * PSTEP - 128.0f;
    const float bxhi = (tx0 + TW - 1) * PSTEP - 128.0f;
    const float bylo = ty0 * PSTEP - 128.0f;
    const float byhi = (ty0 + TH - 1) * PSTEP - 128.0f;

    // q = s*qk equals sigma_px^2 * M^2 before the >=1 clamp
    const float qk = C_ISCALE * C_SPREAD_INV * (C_R2S * d2p) * (C_R2S * d2p);

    __syncthreads();   // cnt visible

    // ---- Phase 1: one scan over the 1024 phosphenes for BOTH batches ----
    // Division/sqrt-free cull; transcendentals only on the survivor path.
    for (int n = tid; n < N_PH; n += 256) {
        const int   e   = idx[n];
        const float s0  = stim[e];             // batch 0
        const float s1  = stim[N_PH + e];      // batch 1
        const float cxs = vx[n] * d2p;
        const float cys = vy[n] * d2p;
        const float Mv  = Marr[n];
        const float M2  = Mv * Mv;
        const float sden0 = fmaxf(s0 * qk, M2);   // sigma0^2 = sden0 / M2
        const float sden1 = fmaxf(s1 * qk, M2);
        const float sdenM = fmaxf(sden0, sden1);

        // 6-sigma footprint on the larger sigma: dd2*M2 > 36*max(sden0,sden1)
        const float ddx = fmaxf(fmaxf(bxlo - cxs, cxs - bxhi), 0.0f);
        const float ddy = fmaxf(fmaxf(bylo - cys, cys - byhi), 0.0f);
        const float dd2 = fmaf(ddx, ddx, ddy * ddy);
        if (dd2 * M2 > 36.0f * sdenM) continue;

        // Survivor-only transcendentals (brightness weights, x2 scale folded in)
        const float t0   = C_SLOPE * (fmaxf(s0 * C_ISCALE - C_RHEO, 0.0f) * C_PWF - C_HALF);
        const float t1   = C_SLOPE * (fmaxf(s1 * C_ISCALE - C_RHEO, 0.0f) * C_PWF - C_HALF);
        const float Bw0  = __fdividef(2.0f, 1.0f + __expf(-t0));
        const float Bw1  = __fdividef(2.0f, 1.0f + __expf(-t1));
        const float m0   = -HALF_LOG2E * __fdividef(M2, sden0);
        const float m1   = -HALF_LOG2E * __fdividef(M2, sden1);

        const int p = atomicAdd(&cnt, 1);
        if (p < CAP) {
            shA[p] = make_float4(cxs, cys, m0, m1);
            shB[p] = make_float2(Bw0, Bw1);
        }
    }
    __syncthreads();

    // ---- Phase 2: one pixel per thread, two batch accumulators ----
    const int w = tx0 + (tid & 31);
    const int h = ty0 + (tid >> 5);
    // Exact grid values (match reference bit-level coordinates):
    // px[y][x] depends only on x (row 0); py[y][x] only on y (col 0).
    const float pxs = px[w] * d2p;
    const float pys = py[h * IMG] * d2p;

    const int nsv = min(cnt, CAP);
    float acc0 = 0.0f, acc1 = 0.0f;
    #pragma unroll 4
    for (int i = 0; i < nsv; i++) {
        const float4 a = shA[i];
        const float2 bw = shB[i];
        const float dx = pxs - a.x;
        const float dy = pys - a.y;
        const float d2 = fmaf(dx, dx, dy * dy);      // shared between batches
        acc0 = fmaf(bw.x, ex2_approx(d2 * a.z), acc0);
        acc1 = fmaf(bw.y, ex2_approx(d2 * a.w), acc1);
    }

    const int pix = h * IMG + w;
    out[pix]        = fminf(acc0, 1.0f);   // acc >= 0 always
    out[NPIX + pix] = fminf(acc1, 1.0f);
}

extern "C" void kernel_launch(void* const* d_in, const int* in_sizes, int n_in,
                              void* d_out, int out_size)
{
    const float* stim = (const float*)d_in[0];   // [2,32,32]
    const float* vx   = (const float*)d_in[1];   // [1024]
    const float* vy   = (const float*)d_in[2];   // [1024]
    const float* M    = (const float*)d_in[3];   // [1024]
    const float* px   = (const float*)d_in[4];   // [256,256]
    const float* py   = (const float*)d_in[5];   // [256,256]
    const int*   idx  = (const int*)  d_in[6];   // [1024]
    float* out = (float*)d_out;                  // [2,1,256,256]

    fused_kernel<<<(IMG / TW) * (IMG / TH), 256>>>(stim, vx, vy, M, px, py, idx, out);
}

// round 9
// speedup vs baseline: 1.1713x; 1.1713x over previous
#include <cuda_runtime.h>

#define N_PH  1024
#define IMG   256
#define NPIX  (IMG * IMG)
#define TW    16          // tile width  (pixels)
#define TH    8           // tile height (pixels)
#define TPIX  (TW * TH)   // 128 pixels per tile
#define CAP   256         // max survivors per tile (analysis bound ~100)

// Constants from the reference
#define C_SPREAD_INV  (1.0f / 0.000675f)
#define C_R2S         0.5f
#define C_SLOPE       19152642.5f
#define C_HALF        1.057e-07f
#define C_RHEO        2.39e-05f
#define C_PWF         (0.00017f * 300.0f)
#define C_ISCALE      8e-05f
#define HALF_LOG2E    0.72134752f   // log2(e)/2 ; exp(-d2/2s2) = exp2(-HALF_LOG2E*d2/s2)

// Single-instruction exp2 (MUFU.EX2), independent of compiler fast-math flags.
__device__ __forceinline__ float ex2_approx(float x) {
    float r;
    asm("ex2.approx.f32 %0, %1;" : "=f"(r) : "f"(x));
    return r;
}

__global__ void __launch_bounds__(256)
fused_kernel(const float* __restrict__ stim,
             const float* __restrict__ vx,
             const float* __restrict__ vy,
             const float* __restrict__ Marr,
             const float* __restrict__ px,
             const float* __restrict__ py,
             const int*   __restrict__ idx,
             float*       __restrict__ out)
{
    __shared__ float4 shA[CAP];     // cxs, cys, m0, m1
    __shared__ float2 shB[CAP];     // Bw0, Bw1 (x2 output scale folded in)
    __shared__ float2 red[TPIX];    // partial sums from upper thread-half
    __shared__ int    cnt;

    const int tid  = threadIdx.x;
    const int tile = blockIdx.x;            // 0..511 : 16 x-tiles * 32 y-tiles
    const int tx0  = (tile & 15) * TW;
    const int ty0  = (tile >> 4) * TH;

    if (tid == 0) cnt = 0;

    // fov = px.max() = last element of ascending linspace
    const float fov = px[NPIX - 1];
    const float d2p = (float)IMG / (2.0f * fov);   // deg2pix

    // Scaled pixel coordinate of column w: px[w]*d2p == w*(256/255) - 128 (±ulp).
    // Approximation error (~1e-3 px) is absorbed by the 6-sigma footprint.
    const float PSTEP = 256.0f / 255.0f;
    const float bxlo = tx0 * PSTEP - 128.0f;
    const float bxhi = (tx0 + TW - 1) * PSTEP - 128.0f;
    const float bylo = ty0 * PSTEP - 128.0f;
    const float byhi = (ty0 + TH - 1) * PSTEP - 128.0f;

    // q = s*qk equals sigma_px^2 * M^2 before the >=1 clamp
    const float qk = C_ISCALE * C_SPREAD_INV * (C_R2S * d2p) * (C_R2S * d2p);

    __syncthreads();   // cnt visible

    // ---- Phase 1: one scan over the 1024 phosphenes for BOTH batches ----
    // Division/sqrt-free cull; transcendentals only on the survivor path.
    for (int n = tid; n < N_PH; n += 256) {
        const int   e   = idx[n];
        const float s0  = stim[e];             // batch 0
        const float s1  = stim[N_PH + e];      // batch 1
        const float cxs = vx[n] * d2p;
        const float cys = vy[n] * d2p;
        const float Mv  = Marr[n];
        const float M2  = Mv * Mv;
        const float sden0 = fmaxf(s0 * qk, M2);   // sigma0^2 = sden0 / M2
        const float sden1 = fmaxf(s1 * qk, M2);
        const float sdenM = fmaxf(sden0, sden1);

        // 6-sigma footprint on the larger sigma: dd2*M2 > 36*max(sden0,sden1)
        const float ddx = fmaxf(fmaxf(bxlo - cxs, cxs - bxhi), 0.0f);
        const float ddy = fmaxf(fmaxf(bylo - cys, cys - byhi), 0.0f);
        const float dd2 = fmaf(ddx, ddx, ddy * ddy);
        if (dd2 * M2 > 36.0f * sdenM) continue;

        // Survivor-only transcendentals (brightness weights, x2 scale folded in)
        const float t0   = C_SLOPE * (fmaxf(s0 * C_ISCALE - C_RHEO, 0.0f) * C_PWF - C_HALF);
        const float t1   = C_SLOPE * (fmaxf(s1 * C_ISCALE - C_RHEO, 0.0f) * C_PWF - C_HALF);
        const float Bw0  = __fdividef(2.0f, 1.0f + __expf(-t0));
        const float Bw1  = __fdividef(2.0f, 1.0f + __expf(-t1));
        const float m0   = -HALF_LOG2E * __fdividef(M2, sden0);
        const float m1   = -HALF_LOG2E * __fdividef(M2, sden1);

        const int p = atomicAdd(&cnt, 1);
        if (p < CAP) {
            shA[p] = make_float4(cxs, cys, m0, m1);
            shB[p] = make_float2(Bw0, Bw1);
        }
    }
    __syncthreads();

    // ---- Phase 2: 128 pixels, survivor list split across the two thread halves ----
    const int pl  = tid & (TPIX - 1);        // pixel index within tile
    const int w   = tx0 + (pl & 15);
    const int h   = ty0 + (pl >> 4);
    // Exact grid values (match reference bit-level coordinates):
    // px[y][x] depends only on x (row 0); py[y][x] only on y (col 0).
    const float pxs = px[w] * d2p;
    const float pys = py[h * IMG] * d2p;

    const int nsv  = min(cnt, CAP);
    const int half = nsv >> 1;
    const int lo   = (tid < TPIX) ? 0    : half;
    const int hi   = (tid < TPIX) ? half : nsv;

    float acc0 = 0.0f, acc1 = 0.0f;
    #pragma unroll 4
    for (int i = lo; i < hi; i++) {
        const float4 a  = shA[i];
        const float2 bw = shB[i];
        const float dx = pxs - a.x;
        const float dy = pys - a.y;
        const float d2 = fmaf(dx, dx, dy * dy);      // shared between batches
        acc0 = fmaf(bw.x, ex2_approx(d2 * a.z), acc0);
        acc1 = fmaf(bw.y, ex2_approx(d2 * a.w), acc1);
    }

    if (tid >= TPIX) red[pl] = make_float2(acc0, acc1);
    __syncthreads();

    if (tid < TPIX) {
        const float2 r = red[pl];
        const int pix = h * IMG + w;
        out[pix]        = fminf(acc0 + r.x, 1.0f);   // acc >= 0 always
        out[NPIX + pix] = fminf(acc1 + r.y, 1.0f);
    }
}

extern "C" void kernel_launch(void* const* d_in, const int* in_sizes, int n_in,
                              void* d_out, int out_size)
{
    const float* stim = (const float*)d_in[0];   // [2,32,32]
    const float* vx   = (const float*)d_in[1];   // [1024]
    const float* vy   = (const float*)d_in[2];   // [1024]
    const float* M    = (const float*)d_in[3];   // [1024]
    const float* px   = (const float*)d_in[4];   // [256,256]
    const float* py   = (const float*)d_in[5];   // [256,256]
    const int*   idx  = (const int*)  d_in[6];   // [1024]
    float* out = (float*)d_out;                  // [2,1,256,256]

    fused_kernel<<<(IMG / TW) * (IMG / TH), 256>>>(stim, vx, vy, M, px, py, idx, out);
}

// round 10
// speedup vs baseline: 1.2362x; 1.0554x over previous
#include <cuda_runtime.h>

#define N_PH  1024
#define IMG   256
#define NPIX  (IMG * IMG)
#define TW    16          // tile width  (pixels)
#define TH    8           // tile height (pixels)
#define TPIX  (TW * TH)   // 128 pixels per tile
#define CAPC  256         // clamped-sigma survivors (foveal; analysis bound ~130)
#define CAPG  128         // general survivors (peripheral; analysis bound ~60)

// Constants from the reference
#define C_SPREAD_INV  (1.0f / 0.000675f)
#define C_R2S         0.5f
#define C_SLOPE       19152642.5f
#define C_HALF        1.057e-07f
#define C_RHEO        2.39e-05f
#define C_PWF         (0.00017f * 300.0f)
#define C_ISCALE      8e-05f
#define HALF_LOG2E    0.72134752f    // log2(e)/2 ; exp(-d2/2s2) = exp2(-HALF_LOG2E*d2/s2)
#define SQRT_HL2E     0.84932184f    // sqrt(HALF_LOG2E): pre-scales coords for clamped list

// Single-instruction exp2 (MUFU.EX2), independent of compiler fast-math flags.
__device__ __forceinline__ float ex2_approx(float x) {
    float r;
    asm("ex2.approx.f32 %0, %1;" : "=f"(r) : "f"(x));
    return r;
}

__global__ void __launch_bounds__(256)
fused_kernel(const float* __restrict__ stim,
             const float* __restrict__ vx,
             const float* __restrict__ vy,
             const float* __restrict__ Marr,
             const float* __restrict__ px,
             const float* __restrict__ py,
             const int*   __restrict__ idx,
             float*       __restrict__ out)
{
    __shared__ float4 shC[CAPC];    // clamped: cxs*S, cys*S, Bw0, Bw1
    __shared__ float4 shG[CAPG];    // general: cxs, cys, m0, m1
    __shared__ float2 shGb[CAPG];   // general: Bw0, Bw1
    __shared__ float2 red[TPIX];    // partial sums from upper thread-half
    __shared__ int    cntc, cntg;

    const int tid  = threadIdx.x;
    const int tile = blockIdx.x;            // 0..511 : 16 x-tiles * 32 y-tiles
    const int tx0  = (tile & 15) * TW;
    const int ty0  = (tile >> 4) * TH;

    if (tid == 0) { cntc = 0; cntg = 0; }

    // fov = px.max() = last element of ascending linspace
    const float fov = px[NPIX - 1];
    const float d2p = (float)IMG / (2.0f * fov);   // deg2pix

    // Scaled pixel coordinate of column w: px[w]*d2p == w*(256/255) - 128 (±ulp).
    // Approximation error (~1e-3 px) is absorbed by the 5.48-sigma footprint.
    const float PSTEP = 256.0f / 255.0f;
    const float bxlo = tx0 * PSTEP - 128.0f;
    const float bxhi = (tx0 + TW - 1) * PSTEP - 128.0f;
    const float bylo = ty0 * PSTEP - 128.0f;
    const float byhi = (ty0 + TH - 1) * PSTEP - 128.0f;

    // q = s*qk equals sigma_px^2 * M^2 before the >=1 clamp
    const float qk = C_ISCALE * C_SPREAD_INV * (C_R2S * d2p) * (C_R2S * d2p);

    __syncthreads();   // counters visible

    // ---- Phase 1: one scan over the 1024 phosphenes for BOTH batches ----
    // Division/sqrt-free cull; transcendentals only on the survivor path.
    for (int n = tid; n < N_PH; n += 256) {
        const int   e   = idx[n];
        const float s0  = stim[e];             // batch 0
        const float s1  = stim[N_PH + e];      // batch 1
        const float cxs = vx[n] * d2p;
        const float cys = vy[n] * d2p;
        const float Mv  = Marr[n];
        const float M2  = Mv * Mv;
        const float qM    = fmaxf(s0, s1) * qk;
        const float sdenM = fmaxf(qM, M2);     // max sigma^2 * M2 across batches

        // 5.48-sigma footprint on the larger sigma (dropped terms < 6e-7 each):
        // dd2 > 30*sigma^2  <=>  dd2*M2 > 30*max(q, M2)
        const float ddx = fmaxf(fmaxf(bxlo - cxs, cxs - bxhi), 0.0f);
        const float ddy = fmaxf(fmaxf(bylo - cys, cys - byhi), 0.0f);
        const float dd2 = fmaf(ddx, ddx, ddy * ddy);
        if (dd2 * M2 > 30.0f * sdenM) continue;

        // Survivor-only transcendentals (brightness weights, x2 scale folded in)
        const float t0  = C_SLOPE * (fmaxf(s0 * C_ISCALE - C_RHEO, 0.0f) * C_PWF - C_HALF);
        const float t1  = C_SLOPE * (fmaxf(s1 * C_ISCALE - C_RHEO, 0.0f) * C_PWF - C_HALF);
        const float Bw0 = __fdividef(2.0f, 1.0f + __expf(-t0));
        const float Bw1 = __fdividef(2.0f, 1.0f + __expf(-t1));

        if (qM <= M2) {
            // Both batches sigma-clamped (all foveal survivors): m0 = m1 =
            // -HALF_LOG2E. One shared exp in phase 2; fold the constant into
            // the coordinates now.
            const int p = atomicAdd(&cntc, 1);
            if (p < CAPC)
                shC[p] = make_float4(cxs * SQRT_HL2E, cys * SQRT_HL2E, Bw0, Bw1);
        } else {
            const float m0 = -HALF_LOG2E * __fdividef(M2, fmaxf(s0 * qk, M2));
            const float m1 = -HALF_LOG2E * __fdividef(M2, fmaxf(s1 * qk, M2));
            const int p = atomicAdd(&cntg, 1);
            if (p < CAPG) {
                shG[p]  = make_float4(cxs, cys, m0, m1);
                shGb[p] = make_float2(Bw0, Bw1);
            }
        }
    }
    __syncthreads();

    // ---- Phase 2: 128 pixels, survivor lists split across the two thread halves ----
    const int pl  = tid & (TPIX - 1);        // pixel index within tile
    const int w   = tx0 + (pl & 15);
    const int h   = ty0 + (pl >> 4);
    // Exact grid values (match reference bit-level coordinates):
    // px[y][x] depends only on x (row 0); py[y][x] only on y (col 0).
    const float pxs = px[w] * d2p;
    const float pys = py[h * IMG] * d2p;
    const float pxq = pxs * SQRT_HL2E;       // pre-scaled for the clamped list
    const float pyq = pys * SQRT_HL2E;

    const int nc = min(cntc, CAPC);
    const int ng = min(cntg, CAPG);
    const bool lowhalf = (tid < TPIX);
    const int c_lo = lowhalf ? 0 : (nc >> 1);
    const int c_hi = lowhalf ? (nc >> 1) : nc;
    const int g_lo = lowhalf ? 0 : (ng >> 1);
    const int g_hi = lowhalf ? (ng >> 1) : ng;

    float acc0 = 0.0f, acc1 = 0.0f;

    // Clamped list: one EX2 serves both batches.
    #pragma unroll 4
    for (int i = c_lo; i < c_hi; i++) {
        const float4 a = shC[i];
        const float dx = pxq - a.x;
        const float dy = pyq - a.y;
        const float d2n = fmaf(dx, -dx, -(dy * dy));  // = -HALF_LOG2E * dist2
        const float g = ex2_approx(d2n);
        acc0 = fmaf(a.z, g, acc0);
        acc1 = fmaf(a.w, g, acc1);
    }

    // General list: two exps (distinct sigmas per batch).
    #pragma unroll 2
    for (int i = g_lo; i < g_hi; i++) {
        const float4 a  = shG[i];
        const float2 bw = shGb[i];
        const float dx = pxs - a.x;
        const float dy = pys - a.y;
        const float d2 = fmaf(dx, dx, dy * dy);
        acc0 = fmaf(bw.x, ex2_approx(d2 * a.z), acc0);
        acc1 = fmaf(bw.y, ex2_approx(d2 * a.w), acc1);
    }

    if (!lowhalf) red[pl] = make_float2(acc0, acc1);
    __syncthreads();

    if (lowhalf) {
        const float2 r = red[pl];
        const int pix = h * IMG + w;
        out[pix]        = fminf(acc0 + r.x, 1.0f);   // acc >= 0 always
        out[NPIX + pix] = fminf(acc1 + r.y, 1.0f);
    }
}

extern "C" void kernel_launch(void* const* d_in, const int* in_sizes, int n_in,
                              void* d_out, int out_size)
{
    const float* stim = (const float*)d_in[0];   // [2,32,32]
    const float* vx   = (const float*)d_in[1];   // [1024]
    const float* vy   = (const float*)d_in[2];   // [1024]
    const float* M    = (const float*)d_in[3];   // [1024]
    const float* px   = (const float*)d_in[4];   // [256,256]
    const float* py   = (const float*)d_in[5];   // [256,256]
    const int*   idx  = (const int*)  d_in[6];   // [1024]
    float* out = (float*)d_out;                  // [2,1,256,256]

    fused_kernel<<<(IMG / TW) * (IMG / TH), 256>>>(stim, vx, vy, M, px, py, idx, out);
}